// round 5
// baseline (speedup 1.0000x reference)
#include <cuda_runtime.h>
#include <cuda_bf16.h>
#include <cstdint>
#include <math.h>

// ============================================================
// Problem constants
// ============================================================
#define MTOT 4096
#define NTOT 8192
#define KTOT 2048
#define NG   16
#define GSZ  (NTOT / NG)   // 512

// GEMM tiling
#define BM 128
#define BN 128
#define BK 64                    // int8 K elements per stage
#define NCHUNK (KTOT / BK)       // 32
#define NSTAGE 4

// Fragment-ordered scratch blocks (per CTA-tile per k-chunk):
//   A block: 2 digits x 2 k32 x 8 m16-atoms x 512B  = 16 KB
//   B block: 2 digits x 2 k32 x 8 n16-pairs x 512B  = 16 KB
#define A_BLK (BM * BK * 2)                    // 16384
#define B_BLK (BN * BK * 2)                    // 16384
#define STAGE_BYTES (A_BLK + B_BLK)            // 32768
#define SMEM_MBAR_OFF (NSTAGE * STAGE_BYTES)   // 131072
#define SMEM_TOTAL (SMEM_MBAR_OFF + 64)

// digit weights: a ~= s * (d1*2^-6 + d2*2^-14)
#define C_BASE  2.44140625e-4f        // 2^-12
#define C_CROSS 9.5367431640625e-7f   // 2^-20

// ============================================================
// Global scratch
// ============================================================
__device__ float g_y[(size_t)MTOT * NTOT];                                    // 128 MB
__device__ __align__(1024) unsigned char g_qA[(size_t)(MTOT / BM) * NCHUNK * A_BLK]; // 16 MB
__device__ __align__(1024) unsigned char g_qB[(size_t)(NTOT / BN) * NCHUNK * B_BLK]; // 32 MB
__device__ float g_sa[MTOT];
__device__ float g_isa[MTOT];
__device__ float g_sb[NTOT];
__device__ float g_isb[NTOT];

// ============================================================
// Helpers
// ============================================================
static __device__ __forceinline__ uint32_t smem_u32(const void* p) {
    uint32_t a;
    asm("{ .reg .u64 t; cvta.to.shared.u64 t, %1; cvt.u32.u64 %0, t; }" : "=r"(a) : "l"(p));
    return a;
}

#define MBARRIER_INIT(addr, cnt) \
    asm volatile("mbarrier.init.shared.b64 [%0], %1;" :: "r"(addr), "r"(cnt) : "memory")

#define MBARRIER_EXPECT_TX(addr, bytes) \
    asm volatile("mbarrier.arrive.expect_tx.shared.b64 _, [%0], %1;" \
                 :: "r"(addr), "r"((uint32_t)(bytes)) : "memory")

#define MBARRIER_WAIT_PARITY(addr, par) do {                                        \
    uint32_t _m = (addr); uint32_t _p = (par); uint32_t _done;                      \
    asm volatile(                                                                    \
        "{\n\t.reg .pred p;\n\t"                                                     \
        "mbarrier.try_wait.parity.acquire.cta.shared::cta.b64 p, [%1], %2;\n\t"      \
        "selp.b32 %0, 1, 0, p;\n\t}"                                                 \
        : "=r"(_done) : "r"(_m), "r"(_p) : "memory");                                \
    if (!_done) {                                                                    \
        asm volatile(                                                                \
            "{\n\t.reg .pred P1;\n\t"                                                \
            "WL_%=:\n\t"                                                             \
            "mbarrier.try_wait.parity.acquire.cta.shared::cta.b64 P1, [%0], %1, 0x989680;\n\t" \
            "@P1 bra.uni WD_%=;\n\t"                                                 \
            "bra.uni WL_%=;\n\t"                                                     \
            "WD_%=:\n\t}"                                                            \
            :: "r"(_m), "r"(_p) : "memory");                                         \
    }                                                                                \
} while (0)

#define BULK_G2S(dst, src, bytes, mbar) \
    asm volatile("cp.async.bulk.shared::cluster.global.mbarrier::complete_tx::bytes " \
                 "[%0], [%1], %2, [%3];" \
                 :: "r"(dst), "l"(src), "r"((uint32_t)(bytes)), "r"(mbar) : "memory")

static __device__ __forceinline__ void lds128(uint32_t addr, uint32_t* r) {
    asm volatile("ld.shared.v4.b32 {%0,%1,%2,%3}, [%4];"
                 : "=r"(r[0]), "=r"(r[1]), "=r"(r[2]), "=r"(r[3]) : "r"(addr));
}

static __device__ __forceinline__ void imma16832(int* c, const uint32_t* a, const uint32_t* b) {
    asm volatile(
        "mma.sync.aligned.m16n8k32.row.col.s32.s8.s8.s32 "
        "{%0,%1,%2,%3}, {%4,%5,%6,%7}, {%8,%9}, {%0,%1,%2,%3};"
        : "+r"(c[0]), "+r"(c[1]), "+r"(c[2]), "+r"(c[3])
        : "r"(a[0]), "r"(a[1]), "r"(a[2]), "r"(a[3]), "r"(b[0]), "r"(b[1]));
}

// ============================================================
// Row-scale kernel: per-row power-of-2 scale s >= max|row|
// 8 rows per 256-thread block (1 warp per row)
// ============================================================
__global__ void __launch_bounds__(256)
rowscale_19688130085476(const float* __restrict__ src, float* __restrict__ s,
                        float* __restrict__ is, int nrows)
{
    int row = blockIdx.x * 8 + (threadIdx.x >> 5);
    if (row >= nrows) return;
    int lane = threadIdx.x & 31;
    const float4* p = (const float4*)(src + (size_t)row * KTOT);
    float m = 0.f;
    #pragma unroll 4
    for (int i = lane; i < KTOT / 4; i += 32) {
        float4 v = __ldg(p + i);
        m = fmaxf(m, fmaxf(fmaxf(fabsf(v.x), fabsf(v.y)), fmaxf(fabsf(v.z), fabsf(v.w))));
    }
    #pragma unroll
    for (int o = 16; o > 0; o >>= 1) m = fmaxf(m, __shfl_xor_sync(0xFFFFFFFFu, m, o));
    if (lane == 0) {
        if (m <= 0.f) { s[row] = 1.f; is[row] = 1.f; }
        else {
            int e;
            frexpf(m, &e);                 // m = f * 2^e, f in [0.5, 1)
            s[row]  = ldexpf(1.f, e);      // 2^e >= m
            is[row] = ldexpf(1.f, -e);
        }
    }
}

// ============================================================
// Quantize A (x): fp32 -> 2-digit int8, fragment-ordered tiles
// Each thread handles one float4 (4 consecutive k)
// ============================================================
__global__ void __launch_bounds__(256)
quantA_19688130085476(const float* __restrict__ x)
{
    int i = blockIdx.x * blockDim.x + threadIdx.x;   // over MTOT*KTOT/4
    if (i >= MTOT * KTOT / 4) return;
    const int row = i >> 9;            // KTOT/4 = 512 quads per row
    const int k   = (i & 511) << 2;

    const float inv = __ldg(g_isa + row) * 64.f;
    float4 v = __ldg((const float4*)x + i);
    float f[4] = {v.x, v.y, v.z, v.w};

    uint32_t w1 = 0, w2 = 0;
    #pragma unroll
    for (int j = 0; j < 4; j++) {
        float a = f[j] * inv;                 // in [-64, 64]
        int d1 = __float2int_rn(a);
        int d2 = __float2int_rn((a - (float)d1) * 256.f);
        d2 = max(-127, min(127, d2));
        w1 |= ((uint32_t)(uint8_t)(int8_t)d1) << (8 * j);
        w2 |= ((uint32_t)(uint8_t)(int8_t)d2) << (8 * j);
    }

    const int m_tile = row >> 7, r = row & 127;
    const int kc = k >> 6, k64 = k & 63, ki = k64 >> 5, kk = k64 & 31;
    const int mi = r >> 4, rr = r & 15;
    const int T   = (rr & 7) * 4 + ((kk & 15) >> 2);
    const int reg = (kk >> 4) * 2 + (rr >> 3);
    const size_t base = (size_t)(m_tile * NCHUNK + kc) * A_BLK;
    const uint32_t frag = (uint32_t)T * 16 + reg * 4;

    *(uint32_t*)(g_qA + base + (uint32_t)((0 * 2 + ki) * 8 + mi) * 512 + frag) = w1;
    *(uint32_t*)(g_qA + base + (uint32_t)((1 * 2 + ki) * 8 + mi) * 512 + frag) = w2;
}

// ============================================================
// Quantize B (W): fp32 -> 2-digit int8, fragment-ordered tiles
// ============================================================
__global__ void __launch_bounds__(256)
quantB_19688130085476(const float* __restrict__ W)
{
    int i = blockIdx.x * blockDim.x + threadIdx.x;   // over NTOT*KTOT/4
    if (i >= NTOT * KTOT / 4) return;
    const int row = i >> 9;
    const int k   = (i & 511) << 2;

    const float inv = __ldg(g_isb + row) * 64.f;
    float4 v = __ldg((const float4*)W + i);
    float f[4] = {v.x, v.y, v.z, v.w};

    uint32_t w1 = 0, w2 = 0;
    #pragma unroll
    for (int j = 0; j < 4; j++) {
        float a = f[j] * inv;
        int d1 = __float2int_rn(a);
        int d2 = __float2int_rn((a - (float)d1) * 256.f);
        d2 = max(-127, min(127, d2));
        w1 |= ((uint32_t)(uint8_t)(int8_t)d1) << (8 * j);
        w2 |= ((uint32_t)(uint8_t)(int8_t)d2) << (8 * j);
    }

    const int n_tile = row >> 7, n = row & 127;
    const int kc = k >> 6, k64 = k & 63, ki = k64 >> 5, kk = k64 & 31;
    const int ni = n >> 4, nn = n & 15, atom = nn >> 3, nc = nn & 7;
    const int T   = nc * 4 + ((kk & 15) >> 2);
    const int reg = kk >> 4;
    const size_t base = (size_t)(n_tile * NCHUNK + kc) * B_BLK;
    const uint32_t frag = (uint32_t)T * 16 + atom * 8 + reg * 4;

    *(uint32_t*)(g_qB + base + (uint32_t)((0 * 2 + ki) * 8 + ni) * 512 + frag) = w1;
    *(uint32_t*)(g_qB + base + (uint32_t)((1 * 2 + ki) * 8 + ni) * 512 + frag) = w2;
}

// ============================================================
// GEMM kernel: y = x @ W^T via 3-pass int8 IMMA
//   grid (NTOT/BN, MTOT/BM) = (64, 32), 256 threads
//   warp tile 32x64: warp_m = wid&3, warp_n = wid>>2
// ============================================================
__global__ void __launch_bounds__(256, 1)
gemm_imma_19688130085476()
{
    extern __shared__ __align__(1024) char smem[];
    const uint32_t sbase = smem_u32(smem);
    const uint32_t mbars = sbase + SMEM_MBAR_OFF;
    const int tid = threadIdx.x;
    const int wid = tid >> 5;
    const int lid = tid & 31;

    const int n_tile = blockIdx.x;
    const int m_tile = blockIdx.y;

    const int warp_m = wid & 3;    // 0..3 -> 32-row slab
    const int warp_n = wid >> 2;   // 0..1 -> 64-col slab

    int accB[2][8][4], accX[2][8][4];
    #pragma unroll
    for (int a = 0; a < 2; a++)
        #pragma unroll
        for (int b = 0; b < 8; b++)
            #pragma unroll
            for (int c = 0; c < 4; c++) { accB[a][b][c] = 0; accX[a][b][c] = 0; }

    if (tid == 0) {
        #pragma unroll
        for (int s = 0; s < NSTAGE; s++) MBARRIER_INIT(mbars + s * 8, 1);
    }
    __syncthreads();

    const unsigned char* Abase = g_qA + (size_t)m_tile * NCHUNK * A_BLK;
    const unsigned char* Bbase = g_qB + (size_t)n_tile * NCHUNK * B_BLK;

    auto produce = [&](int kc, int slot) {
        const uint32_t mb = mbars + slot * 8;
        const uint32_t sd = sbase + slot * STAGE_BYTES;
        MBARRIER_EXPECT_TX(mb, STAGE_BYTES);
        BULK_G2S(sd,         Abase + (size_t)kc * A_BLK, A_BLK, mb);
        BULK_G2S(sd + A_BLK, Bbase + (size_t)kc * B_BLK, B_BLK, mb);
    };

    if (tid == 0) { produce(0, 0); produce(1, 1); produce(2, 2); }

    for (int kc = 0; kc < NCHUNK; kc++) {
        const int slot = kc & 3;
        const uint32_t par = (uint32_t)((kc >> 2) & 1);
        MBARRIER_WAIT_PARITY(mbars + slot * 8, par);
        __syncthreads();  // all warps done with iter kc-1 -> slot (kc+3)%4 free
        if (tid == 0 && kc + 3 < NCHUNK) produce(kc + 3, (kc + 3) & 3);

        const uint32_t slotA = sbase + slot * STAGE_BYTES;
        const uint32_t slotB = slotA + A_BLK;

        #pragma unroll
        for (int ki = 0; ki < 2; ki++) {
            uint32_t A1[2][4], A2[2][4], B1[4][4], B2[4][4];

            #pragma unroll
            for (int mi = 0; mi < 2; mi++) {
                uint32_t sub = (uint32_t)(warp_m * 2 + mi) * 512 + (uint32_t)lid * 16;
                lds128(slotA + (uint32_t)(ki * 8) * 512 + sub,        A1[mi]);   // d=0
                lds128(slotA + (uint32_t)((2 + ki) * 8) * 512 + sub,  A2[mi]);   // d=1
            }
            #pragma unroll
            for (int p = 0; p < 4; p++) {
                uint32_t sub = (uint32_t)(warp_n * 4 + p) * 512 + (uint32_t)lid * 16;
                lds128(slotB + (uint32_t)(ki * 8) * 512 + sub,        B1[p]);
                lds128(slotB + (uint32_t)((2 + ki) * 8) * 512 + sub,  B2[p]);
            }

            #pragma unroll
            for (int mi = 0; mi < 2; mi++)
                #pragma unroll
                for (int p = 0; p < 4; p++)
                    #pragma unroll
                    for (int at = 0; at < 2; at++) {
                        const int na = p * 2 + at;
                        imma16832(accB[mi][na], A1[mi], &B1[p][at * 2]);
                        imma16832(accX[mi][na], A1[mi], &B2[p][at * 2]);
                        imma16832(accX[mi][na], A2[mi], &B1[p][at * 2]);
                    }
        }
    }

    // ---- merge digits, apply scales, store to g_y ----
    const int gq = lid >> 2, qt = lid & 3;
    const int m_base = m_tile * BM + warp_m * 32;
    const int n_base = n_tile * BN + warp_n * 64;

    #pragma unroll
    for (int mi = 0; mi < 2; mi++) {
        const int r0 = m_base + mi * 16 + gq;
        const float sa0 = g_sa[r0];
        const float sa1 = g_sa[r0 + 8];
        #pragma unroll
        for (int na = 0; na < 8; na++) {
            const int c = n_base + na * 8 + qt * 2;
            const float sb0 = g_sb[c], sb1 = g_sb[c + 1];
            float t0 = (float)accB[mi][na][0] * C_BASE + (float)accX[mi][na][0] * C_CROSS;
            float t1 = (float)accB[mi][na][1] * C_BASE + (float)accX[mi][na][1] * C_CROSS;
            float t2 = (float)accB[mi][na][2] * C_BASE + (float)accX[mi][na][2] * C_CROSS;
            float t3 = (float)accB[mi][na][3] * C_BASE + (float)accX[mi][na][3] * C_CROSS;
            __stcs((float2*)(g_y + (size_t)r0 * NTOT + c),
                   make_float2(sa0 * sb0 * t0, sa0 * sb1 * t1));
            __stcs((float2*)(g_y + (size_t)(r0 + 8) * NTOT + c),
                   make_float2(sa1 * sb0 * t2, sa1 * sb1 * t3));
        }
    }
}

// ============================================================
// Epilogue kernel: bias + GroupNorm + SiLU + scale + SiLU
// ============================================================
__global__ void __launch_bounds__(128)
epilogue_kernel_19688130085476(const float* __restrict__ bias,
                               const float* __restrict__ gn_w,
                               const float* __restrict__ gn_b,
                               const float* __restrict__ mult_w,
                               float* __restrict__ out)
{
    const int blk = blockIdx.x;
    const int row = blk >> 4;
    const int g   = blk & 15;
    const int tid = threadIdx.x;
    const int col = g * GSZ + tid * 4;
    const size_t idx = (size_t)row * NTOT + col;

    float4 v  = __ldcs((const float4*)(g_y + idx));
    float4 bb = __ldg((const float4*)(bias + col));
    v.x += bb.x; v.y += bb.y; v.z += bb.z; v.w += bb.w;

    float s  = v.x + v.y + v.z + v.w;
    float ss = v.x * v.x + v.y * v.y + v.z * v.z + v.w * v.w;

    #pragma unroll
    for (int o = 16; o > 0; o >>= 1) {
        s  += __shfl_xor_sync(0xFFFFFFFFu, s, o);
        ss += __shfl_xor_sync(0xFFFFFFFFu, ss, o);
    }
    __shared__ float sh_s[4], sh_ss[4];
    const int w = tid >> 5;
    if ((tid & 31) == 0) { sh_s[w] = s; sh_ss[w] = ss; }
    __syncthreads();
    s  = sh_s[0]  + sh_s[1]  + sh_s[2]  + sh_s[3];
    ss = sh_ss[0] + sh_ss[1] + sh_ss[2] + sh_ss[3];

    const float mean = s * (1.0f / GSZ);
    const float var  = ss * (1.0f / GSZ) - mean * mean;
    const float rinv = rsqrtf(var + 1e-5f);

    float4 gw = __ldg((const float4*)(gn_w + col));
    float4 gb = __ldg((const float4*)(gn_b + col));
    float4 mw = __ldg((const float4*)(mult_w + col));

    float vals[4] = {v.x, v.y, v.z, v.w};
    float gws[4]  = {gw.x, gw.y, gw.z, gw.w};
    float gbs[4]  = {gb.x, gb.y, gb.z, gb.w};
    float mws[4]  = {mw.x, mw.y, mw.z, mw.w};
    float res[4];
    #pragma unroll
    for (int j = 0; j < 4; j++) {
        float n  = (vals[j] - mean) * rinv * gws[j] + gbs[j];
        float s1 = n / (1.0f + __expf(-n));
        float m  = s1 * mws[j];
        res[j]   = m / (1.0f + __expf(-m));
    }
    float4 o4 = make_float4(res[0], res[1], res[2], res[3]);
    *(float4*)(out + idx) = o4;
}

// ============================================================
// Launch
// ============================================================
extern "C" void kernel_launch(void* const* d_in, const int* in_sizes, int n_in,
                              void* d_out, int out_size)
{
    const float* x      = (const float*)d_in[0];
    const float* W      = (const float*)d_in[1];
    const float* bias   = (const float*)d_in[2];
    const float* gn_w   = (const float*)d_in[3];
    const float* gn_b   = (const float*)d_in[4];
    const float* mult_w = (const float*)d_in[5];
    float* out = (float*)d_out;

    cudaFuncSetAttribute(gemm_imma_19688130085476,
                         cudaFuncAttributeMaxDynamicSharedMemorySize, SMEM_TOTAL);

    float *psa, *pisa, *psb, *pisb;
    cudaGetSymbolAddress((void**)&psa, g_sa);
    cudaGetSymbolAddress((void**)&pisa, g_isa);
    cudaGetSymbolAddress((void**)&psb, g_sb);
    cudaGetSymbolAddress((void**)&pisb, g_isb);

    // 1) per-row power-of-2 scales
    rowscale_19688130085476<<<MTOT / 8, 256>>>(x, psa, pisa, MTOT);
    rowscale_19688130085476<<<NTOT / 8, 256>>>(W, psb, pisb, NTOT);

    // 2) quantize into fragment-ordered 2-digit int8 tiles
    quantA_19688130085476<<<(MTOT * KTOT / 4) / 256, 256>>>(x);
    quantB_19688130085476<<<(NTOT * KTOT / 4) / 256, 256>>>(W);

    // 3) GEMM
    dim3 grid(NTOT / BN, MTOT / BM);  // (64, 32)
    gemm_imma_19688130085476<<<grid, 256, SMEM_TOTAL>>>();

    // 4) epilogue
    epilogue_kernel_19688130085476<<<MTOT * NG, 128>>>(bias, gn_w, gn_b, mult_w, out);
}

// round 6
// speedup vs baseline: 3.1605x; 3.1605x over previous
#include <cuda_runtime.h>
#include <cuda_bf16.h>
#include <cstdint>

// ============================================================
// Problem constants
// ============================================================
#define MTOT 4096
#define NTOT 8192
#define KTOT 2048
#define NG   16
#define GSZ  (NTOT / NG)   // 512

// GEMM tiling
#define BM 128
#define BN 256
#define BK 32                    // bf16 K elements per stage
#define NCHUNK (KTOT / BK)       // 64
#define NSTAGE 3

// Tiled+swizzled scratch layout:
//   A block (per m-tile, per k-chunk): 128 rows x 128B ([64B hi | 64B lo]) = 16KB
//   B block (per n-tile, per k-chunk): 256 rows x 128B                     = 32KB
// Rows are SW128-swizzled IN GMEM so a linear bulk copy lands swizzled in SMEM.
#define A_BLK 16384
#define B_BLK 32768
#define STAGE_BYTES (A_BLK + B_BLK)            // 49152
#define SMEM_MBAR_OFF (NSTAGE * STAGE_BYTES)   // 147456
#define SMEM_TOTAL (SMEM_MBAR_OFF + 64)        // 147520

// ============================================================
// Global scratch (static __device__ allowed; no cudaMalloc)
// ============================================================
__device__ float g_y[(size_t)MTOT * NTOT];                              // 128 MB
__device__ __align__(1024) unsigned char g_A[(size_t)MTOT * KTOT * 4];  // 32 MB (hi+lo tiled)
__device__ __align__(1024) unsigned char g_B[(size_t)NTOT * KTOT * 4];  // 64 MB (hi+lo tiled)

// ============================================================
// Helpers
// ============================================================
static __device__ __forceinline__ uint32_t smem_u32(const void* p) {
    uint32_t a;
    asm("{ .reg .u64 t; cvta.to.shared.u64 t, %1; cvt.u32.u64 %0, t; }" : "=r"(a) : "l"(p));
    return a;
}

static __device__ __forceinline__ uint32_t sw128(uint32_t off) {
    return off ^ ((off >> 3) & 0x70);
}

#define MBARRIER_INIT(addr, cnt) \
    asm volatile("mbarrier.init.shared.b64 [%0], %1;" :: "r"(addr), "r"(cnt) : "memory")

#define MBARRIER_ARRIVE(addr) \
    asm volatile("mbarrier.arrive.shared.b64 _, [%0];" :: "r"(addr) : "memory")

#define MBARRIER_EXPECT_TX(addr, bytes) \
    asm volatile("mbarrier.arrive.expect_tx.shared.b64 _, [%0], %1;" \
                 :: "r"(addr), "r"((uint32_t)(bytes)) : "memory")

#define MBARRIER_WAIT_PARITY(addr, par) do {                                        \
    uint32_t _m = (addr); uint32_t _p = (par); uint32_t _done;                      \
    asm volatile(                                                                    \
        "{\n\t.reg .pred p;\n\t"                                                     \
        "mbarrier.try_wait.parity.acquire.cta.shared::cta.b64 p, [%1], %2;\n\t"      \
        "selp.b32 %0, 1, 0, p;\n\t}"                                                 \
        : "=r"(_done) : "r"(_m), "r"(_p) : "memory");                                \
    if (!_done) {                                                                    \
        asm volatile(                                                                \
            "{\n\t.reg .pred P1;\n\t"                                                \
            "WL_%=:\n\t"                                                             \
            "mbarrier.try_wait.parity.acquire.cta.shared::cta.b64 P1, [%0], %1, 0x989680;\n\t" \
            "@P1 bra.uni WD_%=;\n\t"                                                 \
            "bra.uni WL_%=;\n\t"                                                     \
            "WD_%=:\n\t}"                                                            \
            :: "r"(_m), "r"(_p) : "memory");                                         \
    }                                                                                \
} while (0)

#define BULK_G2S(dst, src, bytes, mbar) \
    asm volatile("cp.async.bulk.shared::cluster.global.mbarrier::complete_tx::bytes " \
                 "[%0], [%1], %2, [%3];" \
                 :: "r"(dst), "l"(src), "r"((uint32_t)(bytes)), "r"(mbar) : "memory")

static __device__ __forceinline__ void ldsm4(uint32_t addr, uint32_t* r) {
    asm volatile("ldmatrix.sync.aligned.m8n8.x4.shared.b16 {%0,%1,%2,%3}, [%4];"
                 : "=r"(r[0]), "=r"(r[1]), "=r"(r[2]), "=r"(r[3]) : "r"(addr));
}

static __device__ __forceinline__ void mma16816(float* c, const uint32_t* a, const uint32_t* b) {
    asm volatile(
        "mma.sync.aligned.m16n8k16.row.col.f32.bf16.bf16.f32 "
        "{%0,%1,%2,%3}, {%4,%5,%6,%7}, {%8,%9}, {%0,%1,%2,%3};"
        : "+f"(c[0]), "+f"(c[1]), "+f"(c[2]), "+f"(c[3])
        : "r"(a[0]), "r"(a[1]), "r"(a[2]), "r"(a[3]), "r"(b[0]), "r"(b[1]));
}

static __device__ __forceinline__ uint32_t pack_bf16(__nv_bfloat16 a, __nv_bfloat16 b) {
    uint32_t ua = (uint32_t)__bfloat16_as_ushort(a);
    uint32_t ub = (uint32_t)__bfloat16_as_ushort(b);
    return ua | (ub << 16);
}

// ============================================================
// Conversion kernel: fp32 -> tiled + SW128-swizzled bf16 hi/lo blocks
//   TLOG: log2(rows per tile)   (A: 7 -> 128, B: 8 -> 256)
//   8 elements per thread -> one 16B hi store + one 16B lo store
// ============================================================
template <int TLOG>
__global__ void __launch_bounds__(256)
convert_tiled_19688130085476(const float* __restrict__ src,
                             unsigned char* __restrict__ dst, int n8)
{
    int i = blockIdx.x * blockDim.x + threadIdx.x;
    if (i >= n8) return;

    const int row = i >> 8;           // KTOT/8 = 256 octets per row
    const int q   = i & 255;
    const int k0  = q * 8;
    const int kc  = k0 >> 5;          // k-chunk (BK=32)
    const int c   = k0 & 31;          // 0, 8, 16, 24
    const int tile = row >> TLOG;
    const int r    = row & ((1 << TLOG) - 1);

    float4 v0 = __ldg((const float4*)src + 2 * i);
    float4 v1 = __ldg((const float4*)src + 2 * i + 1);
    float f[8] = {v0.x, v0.y, v0.z, v0.w, v1.x, v1.y, v1.z, v1.w};
    __nv_bfloat16 h[8], l[8];
    #pragma unroll
    for (int j = 0; j < 8; j++) {
        h[j] = __float2bfloat16(f[j]);
        l[j] = __float2bfloat16(f[j] - __bfloat162float(h[j]));
    }

    const size_t base = ((size_t)(tile * NCHUNK + kc)) << (TLOG + 7);
    const uint32_t off_h = (uint32_t)(r * 128 + c * 2);   // 16B aligned
    const uint32_t off_l = off_h + 64;

    uint4 hv, lv;
    hv.x = pack_bf16(h[0], h[1]); hv.y = pack_bf16(h[2], h[3]);
    hv.z = pack_bf16(h[4], h[5]); hv.w = pack_bf16(h[6], h[7]);
    lv.x = pack_bf16(l[0], l[1]); lv.y = pack_bf16(l[2], l[3]);
    lv.z = pack_bf16(l[4], l[5]); lv.w = pack_bf16(l[6], l[7]);
    *(uint4*)(dst + base + sw128(off_h)) = hv;
    *(uint4*)(dst + base + sw128(off_l)) = lv;
}

// ============================================================
// GEMM kernel: y = x @ W^T  via 3-term bf16-split HMMA
//   grid (NTOT/BN, MTOT/BM) = (32, 32), 256 threads
//   Producer/consumer mbarrier ring: no per-iter __syncthreads
// ============================================================
__global__ void __launch_bounds__(256)
gemm_hmma_19688130085476()
{
    extern __shared__ __align__(1024) char smem[];
    const uint32_t sbase = smem_u32(smem);
    const uint32_t mb_full  = sbase + SMEM_MBAR_OFF;        // 3 x 8B
    const uint32_t mb_empty = sbase + SMEM_MBAR_OFF + 24;   // 3 x 8B
    const int tid = threadIdx.x;
    const int wid = tid >> 5;
    const int lid = tid & 31;

    const int n_tile = blockIdx.x;
    const int m_tile = blockIdx.y;
    const int n0 = n_tile * BN;
    const int m0 = m_tile * BM;

    const int warp_m = wid >> 2;   // 0..1 -> 64-row slab
    const int warp_n = wid & 3;    // 0..3 -> 64-col slab

    // ldmatrix lane address components (m8n8.x4 matrix ordering)
    const int a_row_lane   = (lid & 7) + (((lid >> 3) & 1) << 3);
    const int a_chunk_lane = (lid >> 4) & 1;
    const int b_row_lane   = (lid & 7) + (((lid >> 4) & 1) << 3);
    const int b_chunk_lane = (lid >> 3) & 1;

    float acc[4][8][4];
    #pragma unroll
    for (int i = 0; i < 4; i++)
        #pragma unroll
        for (int j = 0; j < 8; j++)
            #pragma unroll
            for (int e = 0; e < 4; e++) acc[i][j][e] = 0.0f;

    if (tid == 0) {
        #pragma unroll
        for (int s = 0; s < NSTAGE; s++) {
            MBARRIER_INIT(mb_full + s * 8, 1);
            MBARRIER_INIT(mb_empty + s * 8, 8);   // one arrive per warp
        }
    }
    __syncthreads();

    const unsigned char* Abase = g_A + ((size_t)m_tile * NCHUNK) * A_BLK;
    const unsigned char* Bbase = g_B + ((size_t)n_tile * NCHUNK) * B_BLK;

    auto produce = [&](int kc, int slot) {
        const uint32_t mb = mb_full + slot * 8;
        const uint32_t sd = sbase + slot * STAGE_BYTES;
        MBARRIER_EXPECT_TX(mb, STAGE_BYTES);
        BULK_G2S(sd,         Abase + (size_t)kc * A_BLK, A_BLK, mb);
        BULK_G2S(sd + A_BLK, Bbase + (size_t)kc * B_BLK, B_BLK, mb);
    };

    // prologue: productions j=0 (slot0), j=1 (slot1) — slots untouched, no wait
    if (tid == 0) { produce(0, 0); produce(1, 1); }

    for (int kc = 0; kc < NCHUNK; kc++) {
        const int slot = kc % NSTAGE;

        // producer: issue production j=kc+2 once slot j%3 is drained.
        // Empty-wait parity: production j into slot s=j%3 is the (j/3)-th reuse;
        // first use (j<3) passes immediately with parity ((j/3)&1)^1 = 1.
        if (tid == 0 && kc + 2 < NCHUNK) {
            const int j = kc + 2;
            MBARRIER_WAIT_PARITY(mb_empty + (j % NSTAGE) * 8,
                                 (uint32_t)(((j / NSTAGE) & 1) ^ 1));
            produce(j, j % NSTAGE);
        }

        // consumer: wait for production kc
        MBARRIER_WAIT_PARITY(mb_full + slot * 8, (uint32_t)((kc / NSTAGE) & 1));

        // ---- compute stage kc ----
        const uint32_t slotA = sbase + slot * STAGE_BYTES;
        const uint32_t slotB = slotA + A_BLK;
        #pragma unroll
        for (int ks = 0; ks < 2; ks++) {
            uint32_t Ah[4][4], Al[4][4], Bh[4][4], Bl[4][4];
            const int a_chunk = 2 * ks + a_chunk_lane;
            const int b_chunk = 2 * ks + b_chunk_lane;

            #pragma unroll
            for (int tm = 0; tm < 4; tm++) {
                uint32_t row = warp_m * 64 + tm * 16 + a_row_lane;
                uint32_t off = row * 128 + a_chunk * 16;
                ldsm4(slotA + sw128(off),      Ah[tm]);
                ldsm4(slotA + sw128(off + 64), Al[tm]);
            }
            #pragma unroll
            for (int tn = 0; tn < 4; tn++) {
                uint32_t row = warp_n * 64 + tn * 16 + b_row_lane;
                uint32_t off = row * 128 + b_chunk * 16;
                ldsm4(slotB + sw128(off),      Bh[tn]);
                ldsm4(slotB + sw128(off + 64), Bl[tn]);
            }

            #pragma unroll
            for (int tm = 0; tm < 4; tm++)
                #pragma unroll
                for (int tn = 0; tn < 4; tn++) {
                    mma16816(acc[tm][2 * tn],     Ah[tm], &Bh[tn][0]);
                    mma16816(acc[tm][2 * tn + 1], Ah[tm], &Bh[tn][2]);
                    mma16816(acc[tm][2 * tn],     Al[tm], &Bh[tn][0]);
                    mma16816(acc[tm][2 * tn + 1], Al[tm], &Bh[tn][2]);
                    mma16816(acc[tm][2 * tn],     Ah[tm], &Bl[tn][0]);
                    mma16816(acc[tm][2 * tn + 1], Ah[tm], &Bl[tn][2]);
                }
        }

        // this warp is done reading slot kc (in-order issue: the MMAs above
        // consumed every ldsm result, so smem reads have completed)
        if (lid == 0) MBARRIER_ARRIVE(mb_empty + slot * 8);
    }

    // ---- write accumulators to g_y (streaming stores; keep L2 for A/B) ----
    const int g = lid >> 2, t = lid & 3;
    #pragma unroll
    for (int tm = 0; tm < 4; tm++) {
        int r0 = m0 + warp_m * 64 + tm * 16 + g;
        #pragma unroll
        for (int tn = 0; tn < 8; tn++) {
            int cc = n0 + warp_n * 64 + tn * 8 + 2 * t;
            float2 v0 = make_float2(acc[tm][tn][0], acc[tm][tn][1]);
            float2 v1 = make_float2(acc[tm][tn][2], acc[tm][tn][3]);
            __stcs((float2*)(g_y + (size_t)r0 * NTOT + cc), v0);
            __stcs((float2*)(g_y + (size_t)(r0 + 8) * NTOT + cc), v1);
        }
    }
}

// ============================================================
// Epilogue: bias + GroupNorm + SiLU + scale + SiLU
// One ROW per 512-thread block; one WARP per group (32 x 16 = 512 cols)
// Pure warp-shuffle reduction: no smem, no __syncthreads
// ============================================================
__global__ void __launch_bounds__(512)
epilogue_kernel_19688130085476(const float* __restrict__ bias,
                               const float* __restrict__ gn_w,
                               const float* __restrict__ gn_b,
                               const float* __restrict__ mult_w,
                               float* __restrict__ out)
{
    const int row  = blockIdx.x;
    const int warp = threadIdx.x >> 5;    // group index 0..15
    const int lane = threadIdx.x & 31;
    const int col  = warp * GSZ + lane * 16;
    const size_t idx = (size_t)row * NTOT + col;

    float4 v[4];
    #pragma unroll
    for (int j = 0; j < 4; j++) {
        v[j] = __ldcs((const float4*)(g_y + idx) + j);
        float4 bb = __ldg((const float4*)(bias + col) + j);
        v[j].x += bb.x; v[j].y += bb.y; v[j].z += bb.z; v[j].w += bb.w;
    }

    float s = 0.f, ss = 0.f;
    #pragma unroll
    for (int j = 0; j < 4; j++) {
        s  += v[j].x + v[j].y + v[j].z + v[j].w;
        ss += v[j].x * v[j].x + v[j].y * v[j].y + v[j].z * v[j].z + v[j].w * v[j].w;
    }
    #pragma unroll
    for (int o = 16; o > 0; o >>= 1) {
        s  += __shfl_xor_sync(0xFFFFFFFFu, s, o);
        ss += __shfl_xor_sync(0xFFFFFFFFu, ss, o);
    }

    const float mean = s * (1.0f / GSZ);
    const float var  = ss * (1.0f / GSZ) - mean * mean;
    const float rinv = rsqrtf(var + 1e-5f);

    #pragma unroll
    for (int j = 0; j < 4; j++) {
        float4 gw = __ldg((const float4*)(gn_w + col) + j);
        float4 gb = __ldg((const float4*)(gn_b + col) + j);
        float4 mw = __ldg((const float4*)(mult_w + col) + j);
        float vals[4] = {v[j].x, v[j].y, v[j].z, v[j].w};
        float gws[4]  = {gw.x, gw.y, gw.z, gw.w};
        float gbs[4]  = {gb.x, gb.y, gb.z, gb.w};
        float mws[4]  = {mw.x, mw.y, mw.z, mw.w};
        float res[4];
        #pragma unroll
        for (int e = 0; e < 4; e++) {
            float n  = (vals[e] - mean) * rinv * gws[e] + gbs[e];
            float s1 = n / (1.0f + __expf(-n));       // SiLU
            float m  = s1 * mws[e];
            res[e]   = m / (1.0f + __expf(-m));       // SiLU
        }
        float4 o4 = make_float4(res[0], res[1], res[2], res[3]);
        *((float4*)(out + idx) + j) = o4;
    }
}

// ============================================================
// Launch
// ============================================================
extern "C" void kernel_launch(void* const* d_in, const int* in_sizes, int n_in,
                              void* d_out, int out_size)
{
    const float* x      = (const float*)d_in[0];
    const float* W      = (const float*)d_in[1];
    const float* bias   = (const float*)d_in[2];
    const float* gn_w   = (const float*)d_in[3];
    const float* gn_b   = (const float*)d_in[4];
    const float* mult_w = (const float*)d_in[5];
    float* out = (float*)d_out;

    cudaFuncSetAttribute(gemm_hmma_19688130085476,
                         cudaFuncAttributeMaxDynamicSharedMemorySize, SMEM_TOTAL);

    unsigned char *pA, *pB;
    cudaGetSymbolAddress((void**)&pA, g_A);
    cudaGetSymbolAddress((void**)&pB, g_B);

    // 1) split-convert x and W into tiled+swizzled hi/lo blocks
    {
        int n8x = MTOT * KTOT / 8;   // 1,048,576
        int n8w = NTOT * KTOT / 8;   // 2,097,152
        convert_tiled_19688130085476<7><<<(n8x + 255) / 256, 256>>>(x, pA, n8x);
        convert_tiled_19688130085476<8><<<(n8w + 255) / 256, 256>>>(W, pB, n8w);
    }

    // 2) GEMM
    dim3 grid(NTOT / BN, MTOT / BM);  // (32, 32)
    gemm_hmma_19688130085476<<<grid, 256, SMEM_TOTAL>>>();

    // 3) epilogue
    epilogue_kernel_19688130085476<<<MTOT, 512>>>(bias, gn_w, gn_b, mult_w, out);
}

// round 7
// speedup vs baseline: 3.2915x; 1.0415x over previous
#include <cuda_runtime.h>
#include <cuda_bf16.h>
#include <cstdint>

// ============================================================
// Problem constants
// ============================================================
#define MTOT 4096
#define NTOT 8192
#define KTOT 2048
#define NG   16
#define GSZ  (NTOT / NG)   // 512

// GEMM tiling
#define BM 128
#define BN 256
#define BK 32                    // bf16 K elements per stage
#define NCHUNK (KTOT / BK)       // 64
#define NSTAGE 3

// Tiled+swizzled scratch layout:
//   A block (per m-tile, per k-chunk): 128 rows x 128B ([64B hi | 64B lo]) = 16KB
//   B block (per n-tile, per k-chunk): 256 rows x 128B                     = 32KB
// Rows are SW128-swizzled IN GMEM so a linear bulk copy lands swizzled in SMEM.
#define A_BLK 16384
#define B_BLK 32768
#define STAGE_BYTES (A_BLK + B_BLK)            // 49152
#define SMEM_MBAR_OFF (NSTAGE * STAGE_BYTES)   // 147456
#define SMEM_TOTAL (SMEM_MBAR_OFF + 64)        // 147520

// ============================================================
// Global scratch (static __device__ allowed; no cudaMalloc)
// ============================================================
__device__ float g_y[(size_t)MTOT * NTOT];                              // 128 MB
__device__ __align__(1024) unsigned char g_A[(size_t)MTOT * KTOT * 4];  // 32 MB (hi+lo tiled)
__device__ __align__(1024) unsigned char g_B[(size_t)NTOT * KTOT * 4];  // 64 MB (hi+lo tiled)

// ============================================================
// Helpers
// ============================================================
static __device__ __forceinline__ uint32_t smem_u32(const void* p) {
    uint32_t a;
    asm("{ .reg .u64 t; cvta.to.shared.u64 t, %1; cvt.u32.u64 %0, t; }" : "=r"(a) : "l"(p));
    return a;
}

static __device__ __forceinline__ uint32_t sw128(uint32_t off) {
    return off ^ ((off >> 3) & 0x70);
}

#define MBARRIER_INIT(addr, cnt) \
    asm volatile("mbarrier.init.shared.b64 [%0], %1;" :: "r"(addr), "r"(cnt) : "memory")

#define MBARRIER_ARRIVE(addr) \
    asm volatile("mbarrier.arrive.shared.b64 _, [%0];" :: "r"(addr) : "memory")

#define MBARRIER_EXPECT_TX(addr, bytes) \
    asm volatile("mbarrier.arrive.expect_tx.shared.b64 _, [%0], %1;" \
                 :: "r"(addr), "r"((uint32_t)(bytes)) : "memory")

#define MBARRIER_WAIT_PARITY(addr, par) do {                                        \
    uint32_t _m = (addr); uint32_t _p = (par); uint32_t _done;                      \
    asm volatile(                                                                    \
        "{\n\t.reg .pred p;\n\t"                                                     \
        "mbarrier.try_wait.parity.acquire.cta.shared::cta.b64 p, [%1], %2;\n\t"      \
        "selp.b32 %0, 1, 0, p;\n\t}"                                                 \
        : "=r"(_done) : "r"(_m), "r"(_p) : "memory");                                \
    if (!_done) {                                                                    \
        asm volatile(                                                                \
            "{\n\t.reg .pred P1;\n\t"                                                \
            "WL_%=:\n\t"                                                             \
            "mbarrier.try_wait.parity.acquire.cta.shared::cta.b64 P1, [%0], %1, 0x989680;\n\t" \
            "@P1 bra.uni WD_%=;\n\t"                                                 \
            "bra.uni WL_%=;\n\t"                                                     \
            "WD_%=:\n\t}"                                                            \
            :: "r"(_m), "r"(_p) : "memory");                                         \
    }                                                                                \
} while (0)

#define BULK_G2S(dst, src, bytes, mbar) \
    asm volatile("cp.async.bulk.shared::cluster.global.mbarrier::complete_tx::bytes " \
                 "[%0], [%1], %2, [%3];" \
                 :: "r"(dst), "l"(src), "r"((uint32_t)(bytes)), "r"(mbar) : "memory")

static __device__ __forceinline__ void ldsm4(uint32_t addr, uint32_t* r) {
    asm volatile("ldmatrix.sync.aligned.m8n8.x4.shared.b16 {%0,%1,%2,%3}, [%4];"
                 : "=r"(r[0]), "=r"(r[1]), "=r"(r[2]), "=r"(r[3]) : "r"(addr));
}

static __device__ __forceinline__ void mma16816(float* c, const uint32_t* a, const uint32_t* b) {
    asm volatile(
        "mma.sync.aligned.m16n8k16.row.col.f32.bf16.bf16.f32 "
        "{%0,%1,%2,%3}, {%4,%5,%6,%7}, {%8,%9}, {%0,%1,%2,%3};"
        : "+f"(c[0]), "+f"(c[1]), "+f"(c[2]), "+f"(c[3])
        : "r"(a[0]), "r"(a[1]), "r"(a[2]), "r"(a[3]), "r"(b[0]), "r"(b[1]));
}

static __device__ __forceinline__ uint32_t pack_bf16(__nv_bfloat16 a, __nv_bfloat16 b) {
    uint32_t ua = (uint32_t)__bfloat16_as_ushort(a);
    uint32_t ub = (uint32_t)__bfloat16_as_ushort(b);
    return ua | (ub << 16);
}

// ============================================================
// Conversion kernel: fp32 -> tiled + SW128-swizzled bf16 hi/lo blocks
//   TLOG: log2(rows per tile)   (A: 7 -> 128, B: 8 -> 256)
//   8 elements per thread -> one 16B hi store + one 16B lo store
// ============================================================
template <int TLOG>
__global__ void __launch_bounds__(256)
convert_tiled_19688130085476(const float* __restrict__ src,
                             unsigned char* __restrict__ dst, int n8)
{
    int i = blockIdx.x * blockDim.x + threadIdx.x;
    if (i >= n8) return;

    const int row = i >> 8;           // KTOT/8 = 256 octets per row
    const int q   = i & 255;
    const int k0  = q * 8;
    const int kc  = k0 >> 5;          // k-chunk (BK=32)
    const int c   = k0 & 31;          // 0, 8, 16, 24
    const int tile = row >> TLOG;
    const int r    = row & ((1 << TLOG) - 1);

    float4 v0 = __ldg((const float4*)src + 2 * i);
    float4 v1 = __ldg((const float4*)src + 2 * i + 1);
    float f[8] = {v0.x, v0.y, v0.z, v0.w, v1.x, v1.y, v1.z, v1.w};
    __nv_bfloat16 h[8], l[8];
    #pragma unroll
    for (int j = 0; j < 8; j++) {
        h[j] = __float2bfloat16(f[j]);
        l[j] = __float2bfloat16(f[j] - __bfloat162float(h[j]));
    }

    const size_t base = ((size_t)(tile * NCHUNK + kc)) << (TLOG + 7);
    const uint32_t off_h = (uint32_t)(r * 128 + c * 2);   // 16B aligned
    const uint32_t off_l = off_h + 64;

    uint4 hv, lv;
    hv.x = pack_bf16(h[0], h[1]); hv.y = pack_bf16(h[2], h[3]);
    hv.z = pack_bf16(h[4], h[5]); hv.w = pack_bf16(h[6], h[7]);
    lv.x = pack_bf16(l[0], l[1]); lv.y = pack_bf16(l[2], l[3]);
    lv.z = pack_bf16(l[4], l[5]); lv.w = pack_bf16(l[6], l[7]);
    *(uint4*)(dst + base + sw128(off_h)) = hv;
    *(uint4*)(dst + base + sw128(off_l)) = lv;
}

// ============================================================
// GEMM kernel: y = x @ W^T  via 3-term bf16-split HMMA
//   grid (NTOT/BN, MTOT/BM) = (32, 32), 256 threads
//   Producer/consumer mbarrier ring: no per-iter __syncthreads
// ============================================================
__global__ void __launch_bounds__(256)
gemm_hmma_19688130085476()
{
    extern __shared__ __align__(1024) char smem[];
    const uint32_t sbase = smem_u32(smem);
    const uint32_t mb_full  = sbase + SMEM_MBAR_OFF;        // 3 x 8B
    const uint32_t mb_empty = sbase + SMEM_MBAR_OFF + 24;   // 3 x 8B
    const int tid = threadIdx.x;
    const int wid = tid >> 5;
    const int lid = tid & 31;

    const int n_tile = blockIdx.x;
    const int m_tile = blockIdx.y;
    const int n0 = n_tile * BN;
    const int m0 = m_tile * BM;

    const int warp_m = wid >> 2;   // 0..1 -> 64-row slab
    const int warp_n = wid & 3;    // 0..3 -> 64-col slab

    // ldmatrix lane address components (m8n8.x4 matrix ordering)
    const int a_row_lane   = (lid & 7) + (((lid >> 3) & 1) << 3);
    const int a_chunk_lane = (lid >> 4) & 1;
    const int b_row_lane   = (lid & 7) + (((lid >> 4) & 1) << 3);
    const int b_chunk_lane = (lid >> 3) & 1;

    float acc[4][8][4];
    #pragma unroll
    for (int i = 0; i < 4; i++)
        #pragma unroll
        for (int j = 0; j < 8; j++)
            #pragma unroll
            for (int e = 0; e < 4; e++) acc[i][j][e] = 0.0f;

    if (tid == 0) {
        #pragma unroll
        for (int s = 0; s < NSTAGE; s++) {
            MBARRIER_INIT(mb_full + s * 8, 1);
            MBARRIER_INIT(mb_empty + s * 8, 8);   // one arrive per warp
        }
    }
    __syncthreads();

    const unsigned char* Abase = g_A + ((size_t)m_tile * NCHUNK) * A_BLK;
    const unsigned char* Bbase = g_B + ((size_t)n_tile * NCHUNK) * B_BLK;

    auto produce = [&](int kc, int slot) {
        const uint32_t mb = mb_full + slot * 8;
        const uint32_t sd = sbase + slot * STAGE_BYTES;
        MBARRIER_EXPECT_TX(mb, STAGE_BYTES);
        BULK_G2S(sd,         Abase + (size_t)kc * A_BLK, A_BLK, mb);
        BULK_G2S(sd + A_BLK, Bbase + (size_t)kc * B_BLK, B_BLK, mb);
    };

    // prologue: productions j=0 (slot0), j=1 (slot1) — slots untouched, no wait
    if (tid == 0) { produce(0, 0); produce(1, 1); }

    for (int kc = 0; kc < NCHUNK; kc++) {
        const int slot = kc % NSTAGE;

        // producer: issue production j=kc+2 once slot j%3 is drained.
        if (tid == 0 && kc + 2 < NCHUNK) {
            const int j = kc + 2;
            MBARRIER_WAIT_PARITY(mb_empty + (j % NSTAGE) * 8,
                                 (uint32_t)(((j / NSTAGE) & 1) ^ 1));
            produce(j, j % NSTAGE);
        }

        // consumer: wait for production kc
        MBARRIER_WAIT_PARITY(mb_full + slot * 8, (uint32_t)((kc / NSTAGE) & 1));

        // ---- compute stage kc ----
        const uint32_t slotA = sbase + slot * STAGE_BYTES;
        const uint32_t slotB = slotA + A_BLK;
        #pragma unroll
        for (int ks = 0; ks < 2; ks++) {
            uint32_t Ah[4][4], Al[4][4], Bh[4][4], Bl[4][4];
            const int a_chunk = 2 * ks + a_chunk_lane;
            const int b_chunk = 2 * ks + b_chunk_lane;

            #pragma unroll
            for (int tm = 0; tm < 4; tm++) {
                uint32_t row = warp_m * 64 + tm * 16 + a_row_lane;
                uint32_t off = row * 128 + a_chunk * 16;
                ldsm4(slotA + sw128(off),      Ah[tm]);
                ldsm4(slotA + sw128(off + 64), Al[tm]);
            }
            #pragma unroll
            for (int tn = 0; tn < 4; tn++) {
                uint32_t row = warp_n * 64 + tn * 16 + b_row_lane;
                uint32_t off = row * 128 + b_chunk * 16;
                ldsm4(slotB + sw128(off),      Bh[tn]);
                ldsm4(slotB + sw128(off + 64), Bl[tn]);
            }

            #pragma unroll
            for (int tm = 0; tm < 4; tm++)
                #pragma unroll
                for (int tn = 0; tn < 4; tn++) {
                    mma16816(acc[tm][2 * tn],     Ah[tm], &Bh[tn][0]);
                    mma16816(acc[tm][2 * tn + 1], Ah[tm], &Bh[tn][2]);
                    mma16816(acc[tm][2 * tn],     Al[tm], &Bh[tn][0]);
                    mma16816(acc[tm][2 * tn + 1], Al[tm], &Bh[tn][2]);
                    mma16816(acc[tm][2 * tn],     Ah[tm], &Bl[tn][0]);
                    mma16816(acc[tm][2 * tn + 1], Ah[tm], &Bl[tn][2]);
                }
        }

        // this warp is done reading slot kc
        if (lid == 0) MBARRIER_ARRIVE(mb_empty + slot * 8);
    }

    // ---- write accumulators to g_y (streaming stores; keep L2 for A/B) ----
    const int g = lid >> 2, t = lid & 3;
    #pragma unroll
    for (int tm = 0; tm < 4; tm++) {
        int r0 = m0 + warp_m * 64 + tm * 16 + g;
        #pragma unroll
        for (int tn = 0; tn < 8; tn++) {
            int cc = n0 + warp_n * 64 + tn * 8 + 2 * t;
            float2 v0 = make_float2(acc[tm][tn][0], acc[tm][tn][1]);
            float2 v1 = make_float2(acc[tm][tn][2], acc[tm][tn][3]);
            __stcs((float2*)(g_y + (size_t)r0 * NTOT + cc), v0);
            __stcs((float2*)(g_y + (size_t)(r0 + 8) * NTOT + cc), v1);
        }
    }
}

// ============================================================
// Epilogue kernel: bias + GroupNorm + SiLU + scale + SiLU
// One block per (row, group): 128 threads x 4 floats = 512
// (round-4 proven layout: lane-contiguous float4 -> coalesced)
// ============================================================
__global__ void __launch_bounds__(128)
epilogue_kernel_19688130085476(const float* __restrict__ bias,
                               const float* __restrict__ gn_w,
                               const float* __restrict__ gn_b,
                               const float* __restrict__ mult_w,
                               float* __restrict__ out)
{
    const int blk = blockIdx.x;
    const int row = blk >> 4;      // 4096 rows
    const int g   = blk & 15;      // 16 groups
    const int tid = threadIdx.x;
    const int col = g * GSZ + tid * 4;
    const size_t idx = (size_t)row * NTOT + col;

    float4 v  = __ldcs((const float4*)(g_y + idx));
    float4 bb = __ldg((const float4*)(bias + col));
    v.x += bb.x; v.y += bb.y; v.z += bb.z; v.w += bb.w;

    float s  = v.x + v.y + v.z + v.w;
    float ss = v.x * v.x + v.y * v.y + v.z * v.z + v.w * v.w;

    #pragma unroll
    for (int o = 16; o > 0; o >>= 1) {
        s  += __shfl_xor_sync(0xFFFFFFFFu, s, o);
        ss += __shfl_xor_sync(0xFFFFFFFFu, ss, o);
    }
    __shared__ float sh_s[4], sh_ss[4];
    const int w = tid >> 5;
    if ((tid & 31) == 0) { sh_s[w] = s; sh_ss[w] = ss; }
    __syncthreads();
    s  = sh_s[0]  + sh_s[1]  + sh_s[2]  + sh_s[3];
    ss = sh_ss[0] + sh_ss[1] + sh_ss[2] + sh_ss[3];

    const float mean = s * (1.0f / GSZ);
    const float var  = ss * (1.0f / GSZ) - mean * mean;
    const float rinv = rsqrtf(var + 1e-5f);

    float4 gw = __ldg((const float4*)(gn_w + col));
    float4 gb = __ldg((const float4*)(gn_b + col));
    float4 mw = __ldg((const float4*)(mult_w + col));

    float vals[4] = {v.x, v.y, v.z, v.w};
    float gws[4]  = {gw.x, gw.y, gw.z, gw.w};
    float gbs[4]  = {gb.x, gb.y, gb.z, gb.w};
    float mws[4]  = {mw.x, mw.y, mw.z, mw.w};
    float res[4];
    #pragma unroll
    for (int j = 0; j < 4; j++) {
        float n  = (vals[j] - mean) * rinv * gws[j] + gbs[j];
        float s1 = n / (1.0f + __expf(-n));       // SiLU
        float m  = s1 * mws[j];
        res[j]   = m / (1.0f + __expf(-m));       // SiLU
    }
    float4 o4 = make_float4(res[0], res[1], res[2], res[3]);
    *(float4*)(out + idx) = o4;
}

// ============================================================
// Launch
// ============================================================
extern "C" void kernel_launch(void* const* d_in, const int* in_sizes, int n_in,
                              void* d_out, int out_size)
{
    const float* x      = (const float*)d_in[0];
    const float* W      = (const float*)d_in[1];
    const float* bias   = (const float*)d_in[2];
    const float* gn_w   = (const float*)d_in[3];
    const float* gn_b   = (const float*)d_in[4];
    const float* mult_w = (const float*)d_in[5];
    float* out = (float*)d_out;

    cudaFuncSetAttribute(gemm_hmma_19688130085476,
                         cudaFuncAttributeMaxDynamicSharedMemorySize, SMEM_TOTAL);

    unsigned char *pA, *pB;
    cudaGetSymbolAddress((void**)&pA, g_A);
    cudaGetSymbolAddress((void**)&pB, g_B);

    // 1) split-convert x and W into tiled+swizzled hi/lo blocks
    {
        int n8x = MTOT * KTOT / 8;   // 1,048,576
        int n8w = NTOT * KTOT / 8;   // 2,097,152
        convert_tiled_19688130085476<7><<<(n8x + 255) / 256, 256>>>(x, pA, n8x);
        convert_tiled_19688130085476<8><<<(n8w + 255) / 256, 256>>>(W, pB, n8w);
    }

    // 2) GEMM
    dim3 grid(NTOT / BN, MTOT / BM);  // (32, 32)
    gemm_hmma_19688130085476<<<grid, 256, SMEM_TOTAL>>>();

    // 3) epilogue
    epilogue_kernel_19688130085476<<<MTOT * NG, 128>>>(bias, gn_w, gn_b, mult_w, out);
}